// round 7
// baseline (speedup 1.0000x reference)
#include <cuda_runtime.h>
#include <cuda_bf16.h>
#include <cuda_fp16.h>
#include <cstdint>

#define NN    32768
#define FIN   256
#define HH    4
#define CC    128
#define HC    512
#define EMAX  524288
#define NEG   0.2f

// ---------------- scratch ----------------
__device__ __half g_hh[(size_t)NN * HC];   // post-GEMM features, fp16
__device__ float g_t[(size_t)NN * CC];
__device__ float g_asrc[NN * HH];
__device__ float g_adst[NN * HH];
__device__ int   g_deg[NN];
__device__ int   g_rowptr[NN + 1];
__device__ int   g_cursor[NN];
__device__ int   g_csr[EMAX + NN];
__device__ float g_bnsum[CC];
__device__ float g_bnsq[CC];
__device__ float g_scale[CC];
__device__ float g_shift[CC];
__device__ int   g_is64;
__device__ int   g_bsum[128];
__device__ __nv_bfloat16 g_Bhi[HC * FIN];
__device__ __nv_bfloat16 g_Blo[HC * FIN];
__device__ __nv_bfloat16 g_Ahi[(size_t)NN * FIN];
__device__ __nv_bfloat16 g_Alo[(size_t)NN * FIN];

__device__ __forceinline__ uint32_t smem_u32(const void* p) {
    uint32_t a;
    asm("{ .reg .u64 t; cvta.to.shared.u64 t, %1; cvt.u32.u64 %0, t; }" : "=r"(a) : "l"(p));
    return a;
}
#define LDSM_X4(r0, r1, r2, r3, addr) \
    asm volatile("ldmatrix.sync.aligned.m8n8.x4.shared.b16 {%0,%1,%2,%3}, [%4];" \
        : "=r"(r0), "=r"(r1), "=r"(r2), "=r"(r3) : "r"(addr))
#define MMA16816(d, a0, a1, a2, a3, b0, b1) \
    asm volatile("mma.sync.aligned.m16n8k16.row.col.f32.bf16.bf16.f32 " \
        "{%0,%1,%2,%3},{%4,%5,%6,%7},{%8,%9},{%0,%1,%2,%3};" \
        : "+f"((d)[0]), "+f"((d)[1]), "+f"((d)[2]), "+f"((d)[3]) \
        : "r"(a0), "r"(a1), "r"(a2), "r"(a3), "r"(b0), "r"(b1))
__device__ __forceinline__ void cp16(uint32_t dst, const void* src) {
    asm volatile("cp.async.cg.shared.global [%0], [%1], 16;" :: "r"(dst), "l"(src));
}
#define CP_COMMIT() asm volatile("cp.async.commit_group;" ::: "memory")

// ---------------- dtype detection ----------------
__global__ void k_detect(const unsigned int* __restrict__ ei32) {
    __shared__ unsigned int s_or[256];
    unsigned int v = 0;
    int t = threadIdx.x;
#pragma unroll
    for (int i = 0; i < 8; i++) v |= ei32[2 * (t * 8 + i) + 1];
    s_or[t] = v;
    __syncthreads();
    for (int o = 128; o > 0; o >>= 1) {
        if (t < o) s_or[t] |= s_or[t + o];
        __syncthreads();
    }
    if (t == 0) g_is64 = (s_or[0] == 0) ? 1 : 0;
}
__device__ __forceinline__ int edge_at(const void* ei, int is64, size_t idx) {
    return is64 ? (int)((const long long*)ei)[idx] : ((const int*)ei)[idx];
}

// ---------------- CSR build ----------------
__global__ void k_init() {
    int i = blockIdx.x * blockDim.x + threadIdx.x;
    if (i < NN) g_deg[i] = 1;
    if (i < CC) { g_bnsum[i] = 0.f; g_bnsq[i] = 0.f; }
}
__global__ void k_hist(const void* __restrict__ ei, int E) {
    int e = blockIdx.x * blockDim.x + threadIdx.x;
    int is64 = g_is64;
    if (e < E) atomicAdd(&g_deg[edge_at(ei, is64, (size_t)E + e)], 1);
}
__global__ void k_scan1() {
    __shared__ int s[256];
    int b = blockIdx.x, t = threadIdx.x;
    s[t] = g_deg[b * 256 + t];
    __syncthreads();
    for (int o = 128; o > 0; o >>= 1) {
        if (t < o) s[t] += s[t + o];
        __syncthreads();
    }
    if (t == 0) g_bsum[b] = s[0];
}
__global__ void k_scan2() {
    __shared__ int s[128];
    int t = threadIdx.x;
    int v = g_bsum[t];
    s[t] = v;
    __syncthreads();
    for (int off = 1; off < 128; off <<= 1) {
        int x = (t >= off) ? s[t - off] : 0;
        __syncthreads();
        s[t] += x;
        __syncthreads();
    }
    g_bsum[t] = s[t] - v;
    if (t == 127) g_rowptr[NN] = s[127];
}
__global__ void k_scan3() {
    __shared__ int s[256];
    int b = blockIdx.x, t = threadIdx.x;
    int i = b * 256 + t;
    int v = g_deg[i];
    s[t] = v;
    __syncthreads();
    for (int off = 1; off < 256; off <<= 1) {
        int x = (t >= off) ? s[t - off] : 0;
        __syncthreads();
        s[t] += x;
        __syncthreads();
    }
    int excl = s[t] - v + g_bsum[b];
    g_rowptr[i] = excl;
    g_cursor[i] = excl;
}
__global__ void k_scatter(const void* __restrict__ ei, int E) {
    int e = blockIdx.x * blockDim.x + threadIdx.x;
    int is64 = g_is64;
    if (e < E) {
        int s = edge_at(ei, is64, e);
        int d = edge_at(ei, is64, (size_t)E + e);
        g_csr[atomicAdd(&g_cursor[d], 1)] = s;
    } else if (e < E + NN) {
        int n = e - E;
        g_csr[atomicAdd(&g_cursor[n], 1)] = n;
    }
}

// ---------------- weight pretranspose + split ----------------
__global__ void k_prep(const float* __restrict__ W, int K, int Nn) {
    __shared__ float tile[32][33];
    int nb = blockIdx.x * 32, kb = blockIdx.y * 32;
    for (int j = threadIdx.y; j < 32; j += 8)
        tile[j][threadIdx.x] = W[(size_t)(kb + j) * Nn + nb + threadIdx.x];
    __syncthreads();
    for (int j = threadIdx.y; j < 32; j += 8) {
        float v = tile[threadIdx.x][j];
        __nv_bfloat16 hi = __float2bfloat16_rn(v);
        __nv_bfloat16 lo = __float2bfloat16_rn(v - __bfloat162float(hi));
        size_t o = (size_t)(nb + j) * K + kb + threadIdx.x;
        g_Bhi[o] = hi;
        g_Blo[o] = lo;
    }
}

// ---------------- activation conversion (BN+ReLU fused) -> bf16 hi/lo --------
template <bool FUSE>
__global__ void k_conv(const float4* __restrict__ src, int kmask4) {
    int i = blockIdx.x * blockDim.x + threadIdx.x;
    float4 v = src[i];
    if (FUSE) {
        int ch = (i & kmask4) * 4;
        v.x = fmaxf(fmaf(v.x, g_scale[ch + 0], g_shift[ch + 0]), 0.f);
        v.y = fmaxf(fmaf(v.y, g_scale[ch + 1], g_shift[ch + 1]), 0.f);
        v.z = fmaxf(fmaf(v.z, g_scale[ch + 2], g_shift[ch + 2]), 0.f);
        v.w = fmaxf(fmaf(v.w, g_scale[ch + 3], g_shift[ch + 3]), 0.f);
    }
    __nv_bfloat162 h0 = __floats2bfloat162_rn(v.x, v.y);
    __nv_bfloat162 h1 = __floats2bfloat162_rn(v.z, v.w);
    __nv_bfloat162 l0 = __floats2bfloat162_rn(v.x - __bfloat162float(h0.x),
                                              v.y - __bfloat162float(h0.y));
    __nv_bfloat162 l1 = __floats2bfloat162_rn(v.z - __bfloat162float(h1.x),
                                              v.w - __bfloat162float(h1.y));
    *(uint2*)&g_Ahi[(size_t)i * 4] = make_uint2(*(uint32_t*)&h0, *(uint32_t*)&h1);
    *(uint2*)&g_Alo[(size_t)i * 4] = make_uint2(*(uint32_t*)&l0, *(uint32_t*)&l1);
}

__global__ void k_zattn() {
    int i = blockIdx.x * blockDim.x + threadIdx.x;
    if (i < NN * HH) { g_asrc[i] = 0.f; g_adst[i] = 0.f; }
}

// ---------------- cp.async double-buffered bf16 mma GEMM ----------------
template <int K, bool ATTN, bool OUTF32>
__global__ void __launch_bounds__(256) k_gemm_m(
    float* __restrict__ C, int Nn,
    const float* __restrict__ attS, const float* __restrict__ attD,
    const float* __restrict__ bias)
{
    constexpr int NC = K / 32;
    constexpr uint32_t STG = 40960;
    constexpr uint32_t OFF_AL = 10240, OFF_BH = 20480, OFF_BL = 30720;
    extern __shared__ __align__(16) char smraw[];
    const uint32_t sb = smem_u32(smraw);

    const int tid = threadIdx.x;
    const int lane = tid & 31;
    const int wid = tid >> 5;
    const int wm = wid & 3, wn = wid >> 2;
    const int row0 = blockIdx.y * 128, col0 = blockIdx.x * 128;

    float d[2][8][4];
#pragma unroll
    for (int i = 0; i < 2; i++)
#pragma unroll
        for (int j = 0; j < 8; j++)
#pragma unroll
            for (int q = 0; q < 4; q++) d[i][j][q] = 0.f;

    const int c0 = tid, c1 = tid + 256;
    const int r0s = c0 >> 2, kb0 = c0 & 3;
    const int r1s = c1 >> 2, kb1 = c1 & 3;

#define STAGE(kc, s) do { \
    uint32_t b = sb + (s) * STG; \
    cp16(b + r0s * 80 + kb0 * 16, &g_Ahi[(size_t)(row0 + r0s) * K + (kc) * 32 + kb0 * 8]); \
    cp16(b + r1s * 80 + kb1 * 16, &g_Ahi[(size_t)(row0 + r1s) * K + (kc) * 32 + kb1 * 8]); \
    cp16(b + OFF_AL + r0s * 80 + kb0 * 16, &g_Alo[(size_t)(row0 + r0s) * K + (kc) * 32 + kb0 * 8]); \
    cp16(b + OFF_AL + r1s * 80 + kb1 * 16, &g_Alo[(size_t)(row0 + r1s) * K + (kc) * 32 + kb1 * 8]); \
    cp16(b + OFF_BH + r0s * 80 + kb0 * 16, &g_Bhi[(size_t)(col0 + r0s) * K + (kc) * 32 + kb0 * 8]); \
    cp16(b + OFF_BH + r1s * 80 + kb1 * 16, &g_Bhi[(size_t)(col0 + r1s) * K + (kc) * 32 + kb1 * 8]); \
    cp16(b + OFF_BL + r0s * 80 + kb0 * 16, &g_Blo[(size_t)(col0 + r0s) * K + (kc) * 32 + kb0 * 8]); \
    cp16(b + OFF_BL + r1s * 80 + kb1 * 16, &g_Blo[(size_t)(col0 + r1s) * K + (kc) * 32 + kb1 * 8]); \
} while (0)

    STAGE(0, 0);
    CP_COMMIT();

    const int a_row = lane & 15, a_col8 = (lane >> 4) * 8;
    const int b_row = ((lane >> 4) << 3) + (lane & 7), b_col8 = ((lane >> 3) & 1) * 8;

    for (int kc = 0; kc < NC; ++kc) {
        if (kc + 1 < NC) {
            STAGE(kc + 1, (kc + 1) & 1);
            CP_COMMIT();
            asm volatile("cp.async.wait_group 1;" ::: "memory");
        } else {
            asm volatile("cp.async.wait_group 0;" ::: "memory");
        }
        __syncthreads();

        const uint32_t bs = sb + (kc & 1) * STG;
#pragma unroll
        for (int kk = 0; kk < 32; kk += 16) {
            uint32_t ah[2][4], al[2][4], bh[8][2], bl[8][2];
#pragma unroll
            for (int mi = 0; mi < 2; mi++) {
                uint32_t off = (uint32_t)((wm * 32 + mi * 16 + a_row) * 40 + kk + a_col8) * 2;
                LDSM_X4(ah[mi][0], ah[mi][1], ah[mi][2], ah[mi][3], bs + off);
                LDSM_X4(al[mi][0], al[mi][1], al[mi][2], al[mi][3], bs + OFF_AL + off);
            }
#pragma unroll
            for (int np = 0; np < 4; np++) {
                uint32_t off = (uint32_t)((wn * 64 + np * 16 + b_row) * 40 + kk + b_col8) * 2;
                uint32_t r0, r1, r2, r3;
                LDSM_X4(r0, r1, r2, r3, bs + OFF_BH + off);
                bh[np * 2][0] = r0; bh[np * 2][1] = r1;
                bh[np * 2 + 1][0] = r2; bh[np * 2 + 1][1] = r3;
                LDSM_X4(r0, r1, r2, r3, bs + OFF_BL + off);
                bl[np * 2][0] = r0; bl[np * 2][1] = r1;
                bl[np * 2 + 1][0] = r2; bl[np * 2 + 1][1] = r3;
            }
#pragma unroll
            for (int mi = 0; mi < 2; mi++)
#pragma unroll
                for (int ni = 0; ni < 8; ni++) {
                    MMA16816(d[mi][ni], ah[mi][0], ah[mi][1], ah[mi][2], ah[mi][3],
                             bh[ni][0], bh[ni][1]);
                    MMA16816(d[mi][ni], ah[mi][0], ah[mi][1], ah[mi][2], ah[mi][3],
                             bl[ni][0], bl[ni][1]);
                    MMA16816(d[mi][ni], al[mi][0], al[mi][1], al[mi][2], al[mi][3],
                             bh[ni][0], bh[ni][1]);
                }
        }
        __syncthreads();
    }
#undef STAGE

    const int er = lane >> 2, ec = (lane & 3) * 2;
#pragma unroll
    for (int mi = 0; mi < 2; mi++) {
        float s0 = 0.f, s1 = 0.f, t0 = 0.f, t1 = 0.f;
#pragma unroll
        for (int ni = 0; ni < 8; ni++) {
            int r = row0 + wm * 32 + mi * 16 + er;
            int c = col0 + wn * 64 + ni * 8 + ec;
            float2 v0 = make_float2(d[mi][ni][0], d[mi][ni][1]);
            float2 v1 = make_float2(d[mi][ni][2], d[mi][ni][3]);
            if (OUTF32) {
                float b0 = __ldg(&bias[c]), b1 = __ldg(&bias[c + 1]);
                v0.x += b0; v0.y += b1; v1.x += b0; v1.y += b1;
                *(float2*)&C[(size_t)r * Nn + c] = v0;
                *(float2*)&C[(size_t)(r + 8) * Nn + c] = v1;
            } else {
                if (ATTN) {
                    int cc = wn * 64 + ni * 8 + ec;
                    int head = blockIdx.x;
                    float a0 = __ldg(&attS[head * CC + cc]);
                    float a1 = __ldg(&attS[head * CC + cc + 1]);
                    float e0 = __ldg(&attD[head * CC + cc]);
                    float e1 = __ldg(&attD[head * CC + cc + 1]);
                    s0 = fmaf(v0.x, a0, fmaf(v0.y, a1, s0));
                    s1 = fmaf(v1.x, a0, fmaf(v1.y, a1, s1));
                    t0 = fmaf(v0.x, e0, fmaf(v0.y, e1, t0));
                    t1 = fmaf(v1.x, e0, fmaf(v1.y, e1, t1));
                }
                *(__half2*)&g_hh[(size_t)r * Nn + c] = __floats2half2_rn(v0.x, v0.y);
                *(__half2*)&g_hh[(size_t)(r + 8) * Nn + c] = __floats2half2_rn(v1.x, v1.y);
            }
        }
        if (ATTN && !OUTF32) {
            s0 += __shfl_xor_sync(0xffffffffu, s0, 1);
            s0 += __shfl_xor_sync(0xffffffffu, s0, 2);
            s1 += __shfl_xor_sync(0xffffffffu, s1, 1);
            s1 += __shfl_xor_sync(0xffffffffu, s1, 2);
            t0 += __shfl_xor_sync(0xffffffffu, t0, 1);
            t0 += __shfl_xor_sync(0xffffffffu, t0, 2);
            t1 += __shfl_xor_sync(0xffffffffu, t1, 1);
            t1 += __shfl_xor_sync(0xffffffffu, t1, 2);
            if ((lane & 3) == 0) {
                int head = blockIdx.x;
                int r = row0 + wm * 32 + mi * 16 + er;
                atomicAdd(&g_asrc[r * 4 + head], s0);
                atomicAdd(&g_adst[r * 4 + head], t0);
                atomicAdd(&g_asrc[(r + 8) * 4 + head], s1);
                atomicAdd(&g_adst[(r + 8) * 4 + head], t1);
            }
        }
    }
}

__device__ __forceinline__ float lrelu(float v) { return v > 0.f ? v : NEG * v; }

// ---------------- segment softmax + aggregation ----------------
// 2 nodes per 256-thread block; 4 warps cooperate per node.
// Passes 1/1b run redundantly in all 4 warps (lane-parallel over edges);
// pass 2 partitions edges across the 4 warps; partials combine via smem.
__global__ void __launch_bounds__(256) k_aggr(const __half* __restrict__ h,
                                              const float* __restrict__ bias)
{
    __shared__ __align__(16) float s_acc[2][4][512];   // [node][warp][head*128+ch]
    __shared__ float s_inv[2][4];
    __shared__ float s_sum[CC], s_sq[CC];
    const int tid = threadIdx.x;
    if (tid < CC) { s_sum[tid] = 0.f; s_sq[tid] = 0.f; }

    const int lane = tid & 31;
    const int w4 = (tid >> 5) & 3;      // warp within node
    const int nd = tid >> 7;            // node slot 0/1
    const int n = blockIdx.x * 2 + nd;
    const int start = g_rowptr[n], end = g_rowptr[n + 1];
    const float4 ad = *(const float4*)&g_adst[n * 4];

    // pass 1: max (all 4 warps redundant, lanes over edges)
    float4 m = make_float4(-1e30f, -1e30f, -1e30f, -1e30f);
    for (int i = start + lane; i < end; i += 32) {
        int s = g_csr[i];
        float4 as = *(const float4*)&g_asrc[s * 4];
        m.x = fmaxf(m.x, lrelu(as.x + ad.x));
        m.y = fmaxf(m.y, lrelu(as.y + ad.y));
        m.z = fmaxf(m.z, lrelu(as.z + ad.z));
        m.w = fmaxf(m.w, lrelu(as.w + ad.w));
    }
#pragma unroll
    for (int o = 16; o > 0; o >>= 1) {
        m.x = fmaxf(m.x, __shfl_xor_sync(0xffffffffu, m.x, o));
        m.y = fmaxf(m.y, __shfl_xor_sync(0xffffffffu, m.y, o));
        m.z = fmaxf(m.z, __shfl_xor_sync(0xffffffffu, m.z, o));
        m.w = fmaxf(m.w, __shfl_xor_sync(0xffffffffu, m.w, o));
    }
    // pass 1b: denom
    float4 ds = make_float4(0.f, 0.f, 0.f, 0.f);
    for (int i = start + lane; i < end; i += 32) {
        int s = g_csr[i];
        float4 as = *(const float4*)&g_asrc[s * 4];
        ds.x += __expf(lrelu(as.x + ad.x) - m.x);
        ds.y += __expf(lrelu(as.y + ad.y) - m.y);
        ds.z += __expf(lrelu(as.z + ad.z) - m.z);
        ds.w += __expf(lrelu(as.w + ad.w) - m.w);
    }
#pragma unroll
    for (int o = 16; o > 0; o >>= 1) {
        ds.x += __shfl_xor_sync(0xffffffffu, ds.x, o);
        ds.y += __shfl_xor_sync(0xffffffffu, ds.y, o);
        ds.z += __shfl_xor_sync(0xffffffffu, ds.z, o);
        ds.w += __shfl_xor_sync(0xffffffffu, ds.w, o);
    }
    if (w4 == 0 && lane == 0) {
        s_inv[nd][0] = 1.f / (ds.x + 1e-16f);
        s_inv[nd][1] = 1.f / (ds.y + 1e-16f);
        s_inv[nd][2] = 1.f / (ds.z + 1e-16f);
        s_inv[nd][3] = 1.f / (ds.w + 1e-16f);
    }

    // pass 2: this warp handles edges start+w4, step 4 (whole warp per edge)
    float4 a0 = make_float4(0.f, 0.f, 0.f, 0.f), a1 = a0, a2 = a0, a3 = a0;
    for (int i = start + w4; i < end; i += 4) {
        int s = g_csr[i];
        float4 as = *(const float4*)&g_asrc[s * 4];
        float w0 = __expf(lrelu(as.x + ad.x) - m.x);
        float w1 = __expf(lrelu(as.y + ad.y) - m.y);
        float w2 = __expf(lrelu(as.z + ad.z) - m.z);
        float w3 = __expf(lrelu(as.w + ad.w) - m.w);
        const uint2* row = (const uint2*)(h + (size_t)s * HC);
        uint2 u;
        float2 f0, f1;
        u = row[lane];
        f0 = __half22float2(*(const __half2*)&u.x);
        f1 = __half22float2(*(const __half2*)&u.y);
        a0.x = fmaf(f0.x, w0, a0.x); a0.y = fmaf(f0.y, w0, a0.y);
        a0.z = fmaf(f1.x, w0, a0.z); a0.w = fmaf(f1.y, w0, a0.w);
        u = row[32 + lane];
        f0 = __half22float2(*(const __half2*)&u.x);
        f1 = __half22float2(*(const __half2*)&u.y);
        a1.x = fmaf(f0.x, w1, a1.x); a1.y = fmaf(f0.y, w1, a1.y);
        a1.z = fmaf(f1.x, w1, a1.z); a1.w = fmaf(f1.y, w1, a1.w);
        u = row[64 + lane];
        f0 = __half22float2(*(const __half2*)&u.x);
        f1 = __half22float2(*(const __half2*)&u.y);
        a2.x = fmaf(f0.x, w2, a2.x); a2.y = fmaf(f0.y, w2, a2.y);
        a2.z = fmaf(f1.x, w2, a2.z); a2.w = fmaf(f1.y, w2, a2.w);
        u = row[96 + lane];
        f0 = __half22float2(*(const __half2*)&u.x);
        f1 = __half22float2(*(const __half2*)&u.y);
        a3.x = fmaf(f0.x, w3, a3.x); a3.y = fmaf(f0.y, w3, a3.y);
        a3.z = fmaf(f1.x, w3, a3.z); a3.w = fmaf(f1.y, w3, a3.w);
    }
    *(float4*)&s_acc[nd][w4][0 * 128 + lane * 4] = a0;
    *(float4*)&s_acc[nd][w4][1 * 128 + lane * 4] = a1;
    *(float4*)&s_acc[nd][w4][2 * 128 + lane * 4] = a2;
    *(float4*)&s_acc[nd][w4][3 * 128 + lane * 4] = a3;
    __syncthreads();

    // combine: thread t -> node (t>>7), channel (t&127)
    {
        const int nd2 = tid >> 7, ch = tid & 127;
        const int n2 = blockIdx.x * 2 + nd2;
        float hsum = 0.f;
#pragma unroll
        for (int hh = 0; hh < 4; hh++) {
            float acc = s_acc[nd2][0][hh * 128 + ch] + s_acc[nd2][1][hh * 128 + ch]
                      + s_acc[nd2][2][hh * 128 + ch] + s_acc[nd2][3][hh * 128 + ch];
            hsum = fmaf(acc, s_inv[nd2][hh], hsum);
        }
        float o = 0.25f * hsum + __ldg(&bias[ch]);
        g_t[(size_t)n2 * CC + ch] = o;
        atomicAdd(&s_sum[ch], o);
        atomicAdd(&s_sq[ch], o * o);
    }
    __syncthreads();
    if (tid < CC) {
        atomicAdd(&g_bnsum[tid], s_sum[tid]);
        atomicAdd(&g_bnsq[tid], s_sq[tid]);
    }
}

__global__ void k_bnfin(const float* __restrict__ g, const float* __restrict__ be) {
    int c = threadIdx.x;
    float mu = g_bnsum[c] * (1.f / NN);
    float var = g_bnsq[c] * (1.f / NN) - mu * mu;
    float sc = g[c] * rsqrtf(var + 1e-5f);
    g_scale[c] = sc;
    g_shift[c] = be[c] - mu * sc;
    g_bnsum[c] = 0.f;
    g_bnsq[c] = 0.f;
}

// ---------------- launch ----------------
extern "C" void kernel_launch(void* const* d_in, const int* in_sizes, int n_in,
                              void* d_out, int out_size)
{
    const float* x   = (const float*)d_in[0];
    const void*  ei  = d_in[1];
    const float* W1  = (const float*)d_in[2];
    const float* as1 = (const float*)d_in[3];
    const float* ad1 = (const float*)d_in[4];
    const float* b1  = (const float*)d_in[5];
    const float* g1  = (const float*)d_in[6];
    const float* be1 = (const float*)d_in[7];
    const float* W2  = (const float*)d_in[8];
    const float* as2 = (const float*)d_in[9];
    const float* ad2 = (const float*)d_in[10];
    const float* b2  = (const float*)d_in[11];
    const float* g2  = (const float*)d_in[12];
    const float* be2 = (const float*)d_in[13];
    const float* Wf  = (const float*)d_in[14];
    const float* bf  = (const float*)d_in[15];
    int E = in_sizes[1] / 2;

    __half* phh = nullptr;
    float* pt = nullptr;
    cudaGetSymbolAddress((void**)&phh, g_hh);
    cudaGetSymbolAddress((void**)&pt, g_t);
    float* out = (float*)d_out;

    constexpr int SMEM = 81920;
    cudaFuncSetAttribute(k_gemm_m<256, true, false>,
                         cudaFuncAttributeMaxDynamicSharedMemorySize, SMEM);
    cudaFuncSetAttribute(k_gemm_m<128, true, false>,
                         cudaFuncAttributeMaxDynamicSharedMemorySize, SMEM);
    cudaFuncSetAttribute(k_gemm_m<128, false, true>,
                         cudaFuncAttributeMaxDynamicSharedMemorySize, SMEM);

    // layer-1 GEMM chain
    k_prep<<<dim3(HC / 32, FIN / 32), dim3(32, 8)>>>(W1, FIN, HC);
    k_zattn<<<NN * HH / 256, 256>>>();
    k_conv<false><<<NN * FIN / 1024, 256>>>((const float4*)x, FIN / 4 - 1);
    k_gemm_m<256, true, false><<<dim3(4, 256), 256, SMEM>>>(nullptr, HC, as1, ad1, nullptr);

    // CSR build
    k_detect<<<1, 256>>>((const unsigned int*)ei);
    k_init<<<NN / 256, 256>>>();
    k_hist<<<(E + 255) / 256, 256>>>(ei, E);
    k_scan1<<<128, 256>>>();
    k_scan2<<<1, 128>>>();
    k_scan3<<<128, 256>>>();
    k_scatter<<<(E + NN + 255) / 256, 256>>>(ei, E);

    k_aggr<<<NN / 2, 256>>>(phh, b1);
    k_bnfin<<<1, 128>>>(g1, be1);

    // layer 2
    k_prep<<<dim3(HC / 32, CC / 32), dim3(32, 8)>>>(W2, CC, HC);
    k_zattn<<<NN * HH / 256, 256>>>();
    k_conv<true><<<NN * CC / 1024, 256>>>((const float4*)pt, CC / 4 - 1);
    k_gemm_m<128, true, false><<<dim3(4, 256), 256, SMEM>>>(nullptr, HC, as2, ad2, nullptr);
    k_aggr<<<NN / 2, 256>>>(phh, b2);
    k_bnfin<<<1, 128>>>(g2, be2);

    // final linear (fp32 out)
    k_prep<<<dim3(CC / 32, CC / 32), dim3(32, 8)>>>(Wf, CC, CC);
    k_conv<true><<<NN * CC / 1024, 256>>>((const float4*)pt, CC / 4 - 1);
    k_gemm_m<128, false, true><<<dim3(1, 256), 256, SMEM>>>(out, CC, nullptr, nullptr, bf);
}

// round 8
// speedup vs baseline: 1.1510x; 1.1510x over previous
#include <cuda_runtime.h>
#include <cuda_bf16.h>
#include <cuda_fp16.h>
#include <cstdint>

#define NN    32768
#define FIN   256
#define HH    4
#define CC    128
#define HC    512
#define EMAX  524288
#define NEG   0.2f

// ---------------- scratch ----------------
__device__ __half g_hh[(size_t)NN * HC];   // post-GEMM features, fp16
__device__ float g_t[(size_t)NN * CC];
__device__ float g_asrc[NN * HH];
__device__ float g_adst[NN * HH];
__device__ int   g_deg[NN];
__device__ int   g_rowptr[NN + 1];
__device__ int   g_cursor[NN];
__device__ int   g_csr[EMAX + NN];
__device__ float g_bnsum[CC];
__device__ float g_bnsq[CC];
__device__ float g_scale[CC];
__device__ float g_shift[CC];
__device__ int   g_is64;
__device__ int   g_bsum[128];
__device__ __nv_bfloat16 g_Bhi[HC * FIN];
__device__ __nv_bfloat16 g_Blo[HC * FIN];
__device__ __nv_bfloat16 g_Ahi[(size_t)NN * FIN];
__device__ __nv_bfloat16 g_Alo[(size_t)NN * FIN];

__device__ __forceinline__ uint32_t smem_u32(const void* p) {
    uint32_t a;
    asm("{ .reg .u64 t; cvta.to.shared.u64 t, %1; cvt.u32.u64 %0, t; }" : "=r"(a) : "l"(p));
    return a;
}
#define LDSM_X4(r0, r1, r2, r3, addr) \
    asm volatile("ldmatrix.sync.aligned.m8n8.x4.shared.b16 {%0,%1,%2,%3}, [%4];" \
        : "=r"(r0), "=r"(r1), "=r"(r2), "=r"(r3) : "r"(addr))
#define MMA16816(d, a0, a1, a2, a3, b0, b1) \
    asm volatile("mma.sync.aligned.m16n8k16.row.col.f32.bf16.bf16.f32 " \
        "{%0,%1,%2,%3},{%4,%5,%6,%7},{%8,%9},{%0,%1,%2,%3};" \
        : "+f"((d)[0]), "+f"((d)[1]), "+f"((d)[2]), "+f"((d)[3]) \
        : "r"(a0), "r"(a1), "r"(a2), "r"(a3), "r"(b0), "r"(b1))
__device__ __forceinline__ void cp16(uint32_t dst, const void* src) {
    asm volatile("cp.async.cg.shared.global [%0], [%1], 16;" :: "r"(dst), "l"(src));
}
#define CP_COMMIT() asm volatile("cp.async.commit_group;" ::: "memory")

// ---------------- dtype detection ----------------
__global__ void k_detect(const unsigned int* __restrict__ ei32) {
    __shared__ unsigned int s_or[256];
    unsigned int v = 0;
    int t = threadIdx.x;
#pragma unroll
    for (int i = 0; i < 8; i++) v |= ei32[2 * (t * 8 + i) + 1];
    s_or[t] = v;
    __syncthreads();
    for (int o = 128; o > 0; o >>= 1) {
        if (t < o) s_or[t] |= s_or[t + o];
        __syncthreads();
    }
    if (t == 0) g_is64 = (s_or[0] == 0) ? 1 : 0;
}
__device__ __forceinline__ int edge_at(const void* ei, int is64, size_t idx) {
    return is64 ? (int)((const long long*)ei)[idx] : ((const int*)ei)[idx];
}

// ---------------- CSR build ----------------
__global__ void k_init() {
    int i = blockIdx.x * blockDim.x + threadIdx.x;
    if (i < NN) g_deg[i] = 1;
    if (i < CC) { g_bnsum[i] = 0.f; g_bnsq[i] = 0.f; }
}
__global__ void k_hist(const void* __restrict__ ei, int E) {
    int e = blockIdx.x * blockDim.x + threadIdx.x;
    int is64 = g_is64;
    if (e < E) atomicAdd(&g_deg[edge_at(ei, is64, (size_t)E + e)], 1);
}
__global__ void k_scan1() {
    __shared__ int s[256];
    int b = blockIdx.x, t = threadIdx.x;
    s[t] = g_deg[b * 256 + t];
    __syncthreads();
    for (int o = 128; o > 0; o >>= 1) {
        if (t < o) s[t] += s[t + o];
        __syncthreads();
    }
    if (t == 0) g_bsum[b] = s[0];
}
__global__ void k_scan2() {
    __shared__ int s[128];
    int t = threadIdx.x;
    int v = g_bsum[t];
    s[t] = v;
    __syncthreads();
    for (int off = 1; off < 128; off <<= 1) {
        int x = (t >= off) ? s[t - off] : 0;
        __syncthreads();
        s[t] += x;
        __syncthreads();
    }
    g_bsum[t] = s[t] - v;
    if (t == 127) g_rowptr[NN] = s[127];
}
__global__ void k_scan3() {
    __shared__ int s[256];
    int b = blockIdx.x, t = threadIdx.x;
    int i = b * 256 + t;
    int v = g_deg[i];
    s[t] = v;
    __syncthreads();
    for (int off = 1; off < 256; off <<= 1) {
        int x = (t >= off) ? s[t - off] : 0;
        __syncthreads();
        s[t] += x;
        __syncthreads();
    }
    int excl = s[t] - v + g_bsum[b];
    g_rowptr[i] = excl;
    g_cursor[i] = excl;
}
__global__ void k_scatter(const void* __restrict__ ei, int E) {
    int e = blockIdx.x * blockDim.x + threadIdx.x;
    int is64 = g_is64;
    if (e < E) {
        int s = edge_at(ei, is64, e);
        int d = edge_at(ei, is64, (size_t)E + e);
        g_csr[atomicAdd(&g_cursor[d], 1)] = s;
    } else if (e < E + NN) {
        int n = e - E;
        g_csr[atomicAdd(&g_cursor[n], 1)] = n;
    }
}

// ---------------- weight pretranspose + split ----------------
__global__ void k_prep(const float* __restrict__ W, int K, int Nn) {
    __shared__ float tile[32][33];
    int nb = blockIdx.x * 32, kb = blockIdx.y * 32;
    for (int j = threadIdx.y; j < 32; j += 8)
        tile[j][threadIdx.x] = W[(size_t)(kb + j) * Nn + nb + threadIdx.x];
    __syncthreads();
    for (int j = threadIdx.y; j < 32; j += 8) {
        float v = tile[threadIdx.x][j];
        __nv_bfloat16 hi = __float2bfloat16_rn(v);
        __nv_bfloat16 lo = __float2bfloat16_rn(v - __bfloat162float(hi));
        size_t o = (size_t)(nb + j) * K + kb + threadIdx.x;
        g_Bhi[o] = hi;
        g_Blo[o] = lo;
    }
}

// ---------------- activation conversion (BN+ReLU fused) -> bf16 hi/lo --------
template <bool FUSE>
__global__ void k_conv(const float4* __restrict__ src, int kmask4) {
    int i = blockIdx.x * blockDim.x + threadIdx.x;
    float4 v = src[i];
    if (FUSE) {
        int ch = (i & kmask4) * 4;
        v.x = fmaxf(fmaf(v.x, g_scale[ch + 0], g_shift[ch + 0]), 0.f);
        v.y = fmaxf(fmaf(v.y, g_scale[ch + 1], g_shift[ch + 1]), 0.f);
        v.z = fmaxf(fmaf(v.z, g_scale[ch + 2], g_shift[ch + 2]), 0.f);
        v.w = fmaxf(fmaf(v.w, g_scale[ch + 3], g_shift[ch + 3]), 0.f);
    }
    __nv_bfloat162 h0 = __floats2bfloat162_rn(v.x, v.y);
    __nv_bfloat162 h1 = __floats2bfloat162_rn(v.z, v.w);
    __nv_bfloat162 l0 = __floats2bfloat162_rn(v.x - __bfloat162float(h0.x),
                                              v.y - __bfloat162float(h0.y));
    __nv_bfloat162 l1 = __floats2bfloat162_rn(v.z - __bfloat162float(h1.x),
                                              v.w - __bfloat162float(h1.y));
    *(uint2*)&g_Ahi[(size_t)i * 4] = make_uint2(*(uint32_t*)&h0, *(uint32_t*)&h1);
    *(uint2*)&g_Alo[(size_t)i * 4] = make_uint2(*(uint32_t*)&l0, *(uint32_t*)&l1);
}

__global__ void k_zattn() {
    int i = blockIdx.x * blockDim.x + threadIdx.x;
    if (i < NN * HH) { g_asrc[i] = 0.f; g_adst[i] = 0.f; }
}

// ---------------- cp.async double-buffered bf16 mma GEMM ----------------
template <int K, bool ATTN, bool OUTF32>
__global__ void __launch_bounds__(256) k_gemm_m(
    float* __restrict__ C, int Nn,
    const float* __restrict__ attS, const float* __restrict__ attD,
    const float* __restrict__ bias)
{
    constexpr int NC = K / 32;
    constexpr uint32_t STG = 40960;
    constexpr uint32_t OFF_AL = 10240, OFF_BH = 20480, OFF_BL = 30720;
    extern __shared__ __align__(16) char smraw[];
    const uint32_t sb = smem_u32(smraw);

    const int tid = threadIdx.x;
    const int lane = tid & 31;
    const int wid = tid >> 5;
    const int wm = wid & 3, wn = wid >> 2;
    const int row0 = blockIdx.y * 128, col0 = blockIdx.x * 128;

    float d[2][8][4];
#pragma unroll
    for (int i = 0; i < 2; i++)
#pragma unroll
        for (int j = 0; j < 8; j++)
#pragma unroll
            for (int q = 0; q < 4; q++) d[i][j][q] = 0.f;

    const int c0 = tid, c1 = tid + 256;
    const int r0s = c0 >> 2, kb0 = c0 & 3;
    const int r1s = c1 >> 2, kb1 = c1 & 3;

#define STAGE(kc, s) do { \
    uint32_t b = sb + (s) * STG; \
    cp16(b + r0s * 80 + kb0 * 16, &g_Ahi[(size_t)(row0 + r0s) * K + (kc) * 32 + kb0 * 8]); \
    cp16(b + r1s * 80 + kb1 * 16, &g_Ahi[(size_t)(row0 + r1s) * K + (kc) * 32 + kb1 * 8]); \
    cp16(b + OFF_AL + r0s * 80 + kb0 * 16, &g_Alo[(size_t)(row0 + r0s) * K + (kc) * 32 + kb0 * 8]); \
    cp16(b + OFF_AL + r1s * 80 + kb1 * 16, &g_Alo[(size_t)(row0 + r1s) * K + (kc) * 32 + kb1 * 8]); \
    cp16(b + OFF_BH + r0s * 80 + kb0 * 16, &g_Bhi[(size_t)(col0 + r0s) * K + (kc) * 32 + kb0 * 8]); \
    cp16(b + OFF_BH + r1s * 80 + kb1 * 16, &g_Bhi[(size_t)(col0 + r1s) * K + (kc) * 32 + kb1 * 8]); \
    cp16(b + OFF_BL + r0s * 80 + kb0 * 16, &g_Blo[(size_t)(col0 + r0s) * K + (kc) * 32 + kb0 * 8]); \
    cp16(b + OFF_BL + r1s * 80 + kb1 * 16, &g_Blo[(size_t)(col0 + r1s) * K + (kc) * 32 + kb1 * 8]); \
} while (0)

    STAGE(0, 0);
    CP_COMMIT();

    const int a_row = lane & 15, a_col8 = (lane >> 4) * 8;
    const int b_row = ((lane >> 4) << 3) + (lane & 7), b_col8 = ((lane >> 3) & 1) * 8;

    for (int kc = 0; kc < NC; ++kc) {
        if (kc + 1 < NC) {
            STAGE(kc + 1, (kc + 1) & 1);
            CP_COMMIT();
            asm volatile("cp.async.wait_group 1;" ::: "memory");
        } else {
            asm volatile("cp.async.wait_group 0;" ::: "memory");
        }
        __syncthreads();

        const uint32_t bs = sb + (kc & 1) * STG;
#pragma unroll
        for (int kk = 0; kk < 32; kk += 16) {
            uint32_t ah[2][4], al[2][4], bh[8][2], bl[8][2];
#pragma unroll
            for (int mi = 0; mi < 2; mi++) {
                uint32_t off = (uint32_t)((wm * 32 + mi * 16 + a_row) * 40 + kk + a_col8) * 2;
                LDSM_X4(ah[mi][0], ah[mi][1], ah[mi][2], ah[mi][3], bs + off);
                LDSM_X4(al[mi][0], al[mi][1], al[mi][2], al[mi][3], bs + OFF_AL + off);
            }
#pragma unroll
            for (int np = 0; np < 4; np++) {
                uint32_t off = (uint32_t)((wn * 64 + np * 16 + b_row) * 40 + kk + b_col8) * 2;
                uint32_t r0, r1, r2, r3;
                LDSM_X4(r0, r1, r2, r3, bs + OFF_BH + off);
                bh[np * 2][0] = r0; bh[np * 2][1] = r1;
                bh[np * 2 + 1][0] = r2; bh[np * 2 + 1][1] = r3;
                LDSM_X4(r0, r1, r2, r3, bs + OFF_BL + off);
                bl[np * 2][0] = r0; bl[np * 2][1] = r1;
                bl[np * 2 + 1][0] = r2; bl[np * 2 + 1][1] = r3;
            }
#pragma unroll
            for (int mi = 0; mi < 2; mi++)
#pragma unroll
                for (int ni = 0; ni < 8; ni++) {
                    MMA16816(d[mi][ni], ah[mi][0], ah[mi][1], ah[mi][2], ah[mi][3],
                             bh[ni][0], bh[ni][1]);
                    MMA16816(d[mi][ni], ah[mi][0], ah[mi][1], ah[mi][2], ah[mi][3],
                             bl[ni][0], bl[ni][1]);
                    MMA16816(d[mi][ni], al[mi][0], al[mi][1], al[mi][2], al[mi][3],
                             bh[ni][0], bh[ni][1]);
                }
        }
        __syncthreads();
    }
#undef STAGE

    const int er = lane >> 2, ec = (lane & 3) * 2;
#pragma unroll
    for (int mi = 0; mi < 2; mi++) {
        float s0 = 0.f, s1 = 0.f, t0 = 0.f, t1 = 0.f;
#pragma unroll
        for (int ni = 0; ni < 8; ni++) {
            int r = row0 + wm * 32 + mi * 16 + er;
            int c = col0 + wn * 64 + ni * 8 + ec;
            float2 v0 = make_float2(d[mi][ni][0], d[mi][ni][1]);
            float2 v1 = make_float2(d[mi][ni][2], d[mi][ni][3]);
            if (OUTF32) {
                float b0 = __ldg(&bias[c]), b1 = __ldg(&bias[c + 1]);
                v0.x += b0; v0.y += b1; v1.x += b0; v1.y += b1;
                *(float2*)&C[(size_t)r * Nn + c] = v0;
                *(float2*)&C[(size_t)(r + 8) * Nn + c] = v1;
            } else {
                if (ATTN) {
                    int cc = wn * 64 + ni * 8 + ec;
                    int head = blockIdx.x;
                    float a0 = __ldg(&attS[head * CC + cc]);
                    float a1 = __ldg(&attS[head * CC + cc + 1]);
                    float e0 = __ldg(&attD[head * CC + cc]);
                    float e1 = __ldg(&attD[head * CC + cc + 1]);
                    s0 = fmaf(v0.x, a0, fmaf(v0.y, a1, s0));
                    s1 = fmaf(v1.x, a0, fmaf(v1.y, a1, s1));
                    t0 = fmaf(v0.x, e0, fmaf(v0.y, e1, t0));
                    t1 = fmaf(v1.x, e0, fmaf(v1.y, e1, t1));
                }
                *(__half2*)&g_hh[(size_t)r * Nn + c] = __floats2half2_rn(v0.x, v0.y);
                *(__half2*)&g_hh[(size_t)(r + 8) * Nn + c] = __floats2half2_rn(v1.x, v1.y);
            }
        }
        if (ATTN && !OUTF32) {
            s0 += __shfl_xor_sync(0xffffffffu, s0, 1);
            s0 += __shfl_xor_sync(0xffffffffu, s0, 2);
            s1 += __shfl_xor_sync(0xffffffffu, s1, 1);
            s1 += __shfl_xor_sync(0xffffffffu, s1, 2);
            t0 += __shfl_xor_sync(0xffffffffu, t0, 1);
            t0 += __shfl_xor_sync(0xffffffffu, t0, 2);
            t1 += __shfl_xor_sync(0xffffffffu, t1, 1);
            t1 += __shfl_xor_sync(0xffffffffu, t1, 2);
            if ((lane & 3) == 0) {
                int head = blockIdx.x;
                int r = row0 + wm * 32 + mi * 16 + er;
                atomicAdd(&g_asrc[r * 4 + head], s0);
                atomicAdd(&g_adst[r * 4 + head], t0);
                atomicAdd(&g_asrc[(r + 8) * 4 + head], s1);
                atomicAdd(&g_adst[(r + 8) * 4 + head], t1);
            }
        }
    }
}

__device__ __forceinline__ float lrelu(float v) { return v > 0.f ? v : NEG * v; }

// ---------------- segment softmax + aggregation ----------------
// 2048 blocks x 256 threads; each block grid-strides over 8 node-pairs.
// Per pair: 4 warps/node; pass1/1b redundant (lane-parallel), pass2 edge-split
// across the 4 warps; combine via smem. BN stats accumulate in smem across all
// 8 pairs, single global flush per block (eliminates R7's atomic storm).
__global__ void __launch_bounds__(256) k_aggr(const __half* __restrict__ h,
                                              const float* __restrict__ bias)
{
    __shared__ __align__(16) float s_acc[2][4][512];
    __shared__ float s_inv[2][4];
    __shared__ float s_sum[CC], s_sq[CC];
    const int tid = threadIdx.x;
    if (tid < CC) { s_sum[tid] = 0.f; s_sq[tid] = 0.f; }

    const int lane = tid & 31;
    const int w4 = (tid >> 5) & 3;
    const int nd = tid >> 7;
    const int ch = tid & 127;

    for (int it = 0; it < 8; ++it) {
        const int n = blockIdx.x * 16 + it * 2 + nd;
        const int start = g_rowptr[n], end = g_rowptr[n + 1];
        const float4 ad = *(const float4*)&g_adst[n * 4];

        // pass 1: max (redundant in 4 warps, lanes over edges)
        float4 m = make_float4(-1e30f, -1e30f, -1e30f, -1e30f);
        for (int i = start + lane; i < end; i += 32) {
            int s = g_csr[i];
            float4 as = *(const float4*)&g_asrc[s * 4];
            m.x = fmaxf(m.x, lrelu(as.x + ad.x));
            m.y = fmaxf(m.y, lrelu(as.y + ad.y));
            m.z = fmaxf(m.z, lrelu(as.z + ad.z));
            m.w = fmaxf(m.w, lrelu(as.w + ad.w));
        }
#pragma unroll
        for (int o = 16; o > 0; o >>= 1) {
            m.x = fmaxf(m.x, __shfl_xor_sync(0xffffffffu, m.x, o));
            m.y = fmaxf(m.y, __shfl_xor_sync(0xffffffffu, m.y, o));
            m.z = fmaxf(m.z, __shfl_xor_sync(0xffffffffu, m.z, o));
            m.w = fmaxf(m.w, __shfl_xor_sync(0xffffffffu, m.w, o));
        }
        // pass 1b: denom
        float4 ds = make_float4(0.f, 0.f, 0.f, 0.f);
        for (int i = start + lane; i < end; i += 32) {
            int s = g_csr[i];
            float4 as = *(const float4*)&g_asrc[s * 4];
            ds.x += __expf(lrelu(as.x + ad.x) - m.x);
            ds.y += __expf(lrelu(as.y + ad.y) - m.y);
            ds.z += __expf(lrelu(as.z + ad.z) - m.z);
            ds.w += __expf(lrelu(as.w + ad.w) - m.w);
        }
#pragma unroll
        for (int o = 16; o > 0; o >>= 1) {
            ds.x += __shfl_xor_sync(0xffffffffu, ds.x, o);
            ds.y += __shfl_xor_sync(0xffffffffu, ds.y, o);
            ds.z += __shfl_xor_sync(0xffffffffu, ds.z, o);
            ds.w += __shfl_xor_sync(0xffffffffu, ds.w, o);
        }
        if (w4 == 0 && lane == 0) {
            s_inv[nd][0] = 1.f / (ds.x + 1e-16f);
            s_inv[nd][1] = 1.f / (ds.y + 1e-16f);
            s_inv[nd][2] = 1.f / (ds.z + 1e-16f);
            s_inv[nd][3] = 1.f / (ds.w + 1e-16f);
        }

        // pass 2: edges start+w4, step 4 (whole warp per edge, fp16 gather)
        float4 a0 = make_float4(0.f, 0.f, 0.f, 0.f), a1 = a0, a2 = a0, a3 = a0;
        for (int i = start + w4; i < end; i += 4) {
            int s = g_csr[i];
            float4 as = *(const float4*)&g_asrc[s * 4];
            float w0 = __expf(lrelu(as.x + ad.x) - m.x);
            float w1 = __expf(lrelu(as.y + ad.y) - m.y);
            float w2 = __expf(lrelu(as.z + ad.z) - m.z);
            float w3 = __expf(lrelu(as.w + ad.w) - m.w);
            const uint2* row = (const uint2*)(h + (size_t)s * HC);
            uint2 u;
            float2 f0, f1;
            u = row[lane];
            f0 = __half22float2(*(const __half2*)&u.x);
            f1 = __half22float2(*(const __half2*)&u.y);
            a0.x = fmaf(f0.x, w0, a0.x); a0.y = fmaf(f0.y, w0, a0.y);
            a0.z = fmaf(f1.x, w0, a0.z); a0.w = fmaf(f1.y, w0, a0.w);
            u = row[32 + lane];
            f0 = __half22float2(*(const __half2*)&u.x);
            f1 = __half22float2(*(const __half2*)&u.y);
            a1.x = fmaf(f0.x, w1, a1.x); a1.y = fmaf(f0.y, w1, a1.y);
            a1.z = fmaf(f1.x, w1, a1.z); a1.w = fmaf(f1.y, w1, a1.w);
            u = row[64 + lane];
            f0 = __half22float2(*(const __half2*)&u.x);
            f1 = __half22float2(*(const __half2*)&u.y);
            a2.x = fmaf(f0.x, w2, a2.x); a2.y = fmaf(f0.y, w2, a2.y);
            a2.z = fmaf(f1.x, w2, a2.z); a2.w = fmaf(f1.y, w2, a2.w);
            u = row[96 + lane];
            f0 = __half22float2(*(const __half2*)&u.x);
            f1 = __half22float2(*(const __half2*)&u.y);
            a3.x = fmaf(f0.x, w3, a3.x); a3.y = fmaf(f0.y, w3, a3.y);
            a3.z = fmaf(f1.x, w3, a3.z); a3.w = fmaf(f1.y, w3, a3.w);
        }
        *(float4*)&s_acc[nd][w4][0 * 128 + lane * 4] = a0;
        *(float4*)&s_acc[nd][w4][1 * 128 + lane * 4] = a1;
        *(float4*)&s_acc[nd][w4][2 * 128 + lane * 4] = a2;
        *(float4*)&s_acc[nd][w4][3 * 128 + lane * 4] = a3;
        __syncthreads();

        // combine: thread -> (node nd, channel ch)
        {
            const int n2 = blockIdx.x * 16 + it * 2 + nd;
            float hsum = 0.f;
#pragma unroll
            for (int hh = 0; hh < 4; hh++) {
                float acc = s_acc[nd][0][hh * 128 + ch] + s_acc[nd][1][hh * 128 + ch]
                          + s_acc[nd][2][hh * 128 + ch] + s_acc[nd][3][hh * 128 + ch];
                hsum = fmaf(acc, s_inv[nd][hh], hsum);
            }
            float o = 0.25f * hsum + __ldg(&bias[ch]);
            g_t[(size_t)n2 * CC + ch] = o;
            atomicAdd(&s_sum[ch], o);
            atomicAdd(&s_sq[ch], o * o);
        }
        __syncthreads();
    }
    if (tid < CC) {
        atomicAdd(&g_bnsum[tid], s_sum[tid]);
        atomicAdd(&g_bnsq[tid], s_sq[tid]);
    }
}

__global__ void k_bnfin(const float* __restrict__ g, const float* __restrict__ be) {
    int c = threadIdx.x;
    float mu = g_bnsum[c] * (1.f / NN);
    float var = g_bnsq[c] * (1.f / NN) - mu * mu;
    float sc = g[c] * rsqrtf(var + 1e-5f);
    g_scale[c] = sc;
    g_shift[c] = be[c] - mu * sc;
    g_bnsum[c] = 0.f;
    g_bnsq[c] = 0.f;
}

// ---------------- launch ----------------
extern "C" void kernel_launch(void* const* d_in, const int* in_sizes, int n_in,
                              void* d_out, int out_size)
{
    const float* x   = (const float*)d_in[0];
    const void*  ei  = d_in[1];
    const float* W1  = (const float*)d_in[2];
    const float* as1 = (const float*)d_in[3];
    const float* ad1 = (const float*)d_in[4];
    const float* b1  = (const float*)d_in[5];
    const float* g1  = (const float*)d_in[6];
    const float* be1 = (const float*)d_in[7];
    const float* W2  = (const float*)d_in[8];
    const float* as2 = (const float*)d_in[9];
    const float* ad2 = (const float*)d_in[10];
    const float* b2  = (const float*)d_in[11];
    const float* g2  = (const float*)d_in[12];
    const float* be2 = (const float*)d_in[13];
    const float* Wf  = (const float*)d_in[14];
    const float* bf  = (const float*)d_in[15];
    int E = in_sizes[1] / 2;

    __half* phh = nullptr;
    float* pt = nullptr;
    cudaGetSymbolAddress((void**)&phh, g_hh);
    cudaGetSymbolAddress((void**)&pt, g_t);
    float* out = (float*)d_out;

    constexpr int SMEM = 81920;
    cudaFuncSetAttribute(k_gemm_m<256, true, false>,
                         cudaFuncAttributeMaxDynamicSharedMemorySize, SMEM);
    cudaFuncSetAttribute(k_gemm_m<128, true, false>,
                         cudaFuncAttributeMaxDynamicSharedMemorySize, SMEM);
    cudaFuncSetAttribute(k_gemm_m<128, false, true>,
                         cudaFuncAttributeMaxDynamicSharedMemorySize, SMEM);

    // layer-1 GEMM chain
    k_prep<<<dim3(HC / 32, FIN / 32), dim3(32, 8)>>>(W1, FIN, HC);
    k_zattn<<<NN * HH / 256, 256>>>();
    k_conv<false><<<NN * FIN / 1024, 256>>>((const float4*)x, FIN / 4 - 1);
    k_gemm_m<256, true, false><<<dim3(4, 256), 256, SMEM>>>(nullptr, HC, as1, ad1, nullptr);

    // CSR build
    k_detect<<<1, 256>>>((const unsigned int*)ei);
    k_init<<<NN / 256, 256>>>();
    k_hist<<<(E + 255) / 256, 256>>>(ei, E);
    k_scan1<<<128, 256>>>();
    k_scan2<<<1, 128>>>();
    k_scan3<<<128, 256>>>();
    k_scatter<<<(E + NN + 255) / 256, 256>>>(ei, E);

    k_aggr<<<2048, 256>>>(phh, b1);
    k_bnfin<<<1, 128>>>(g1, be1);

    // layer 2
    k_prep<<<dim3(HC / 32, CC / 32), dim3(32, 8)>>>(W2, CC, HC);
    k_zattn<<<NN * HH / 256, 256>>>();
    k_conv<true><<<NN * CC / 1024, 256>>>((const float4*)pt, CC / 4 - 1);
    k_gemm_m<128, true, false><<<dim3(4, 256), 256, SMEM>>>(nullptr, HC, as2, ad2, nullptr);
    k_aggr<<<2048, 256>>>(phh, b2);
    k_bnfin<<<1, 128>>>(g2, be2);

    // final linear (fp32 out)
    k_prep<<<dim3(CC / 32, CC / 32), dim3(32, 8)>>>(Wf, CC, CC);
    k_conv<true><<<NN * CC / 1024, 256>>>((const float4*)pt, CC / 4 - 1);
    k_gemm_m<128, false, true><<<dim3(1, 256), 256, SMEM>>>(out, CC, nullptr, nullptr, bf);
}

// round 9
// speedup vs baseline: 1.3157x; 1.1431x over previous
#include <cuda_runtime.h>
#include <cuda_bf16.h>
#include <cstdint>

#define NN    32768
#define FIN   256
#define HH    4
#define CC    128
#define HC    512
#define EMAX  524288
#define NEG   0.2f

// ---------------- scratch ----------------
__device__ float g_h[(size_t)NN * HC];     // post-GEMM features fp32
__device__ float g_t[(size_t)NN * CC];
__device__ float g_asrc[NN * HH];
__device__ float g_adst[NN * HH];
__device__ int   g_deg[NN];
__device__ int   g_rowptr[NN + 1];
__device__ int   g_cursor[NN];
__device__ int   g_csr[EMAX + NN];
__device__ float g_bnsum[CC];
__device__ float g_bnsq[CC];
__device__ float g_scale[CC];
__device__ float g_shift[CC];
__device__ int   g_is64;
__device__ int   g_bsum[128];
__device__ __nv_bfloat16 g_Bhi[HC * FIN];
__device__ __nv_bfloat16 g_Blo[HC * FIN];
__device__ __nv_bfloat16 g_Ahi[(size_t)NN * FIN];
__device__ __nv_bfloat16 g_Alo[(size_t)NN * FIN];

__device__ __forceinline__ uint32_t smem_u32(const void* p) {
    uint32_t a;
    asm("{ .reg .u64 t; cvta.to.shared.u64 t, %1; cvt.u32.u64 %0, t; }" : "=r"(a) : "l"(p));
    return a;
}
#define LDSM_X4(r0, r1, r2, r3, addr) \
    asm volatile("ldmatrix.sync.aligned.m8n8.x4.shared.b16 {%0,%1,%2,%3}, [%4];" \
        : "=r"(r0), "=r"(r1), "=r"(r2), "=r"(r3) : "r"(addr))
#define MMA16816(d, a0, a1, a2, a3, b0, b1) \
    asm volatile("mma.sync.aligned.m16n8k16.row.col.f32.bf16.bf16.f32 " \
        "{%0,%1,%2,%3},{%4,%5,%6,%7},{%8,%9},{%0,%1,%2,%3};" \
        : "+f"((d)[0]), "+f"((d)[1]), "+f"((d)[2]), "+f"((d)[3]) \
        : "r"(a0), "r"(a1), "r"(a2), "r"(a3), "r"(b0), "r"(b1))
__device__ __forceinline__ void cp16(uint32_t dst, const void* src) {
    asm volatile("cp.async.cg.shared.global [%0], [%1], 16;" :: "r"(dst), "l"(src));
}
#define CP_COMMIT() asm volatile("cp.async.commit_group;" ::: "memory")

__device__ __forceinline__ int edge_at(const void* ei, int is64, size_t idx) {
    return is64 ? (int)((const long long*)ei)[idx] : ((const int*)ei)[idx];
}

// ---------------- init + dtype detection (merged) ----------------
__global__ void k_initdet(const unsigned int* __restrict__ ei32) {
    __shared__ unsigned int s_or[256];
    int i = blockIdx.x * blockDim.x + threadIdx.x;
    if (i < NN) g_deg[i] = 1;
    if (i < CC) { g_bnsum[i] = 0.f; g_bnsq[i] = 0.f; }
    if (blockIdx.x == 0) {
        unsigned int v = 0;
        int t = threadIdx.x;
#pragma unroll
        for (int k = 0; k < 8; k++) v |= ei32[2 * (t * 8 + k) + 1];
        s_or[t] = v;
        __syncthreads();
        for (int o = 128; o > 0; o >>= 1) {
            if (t < o) s_or[t] |= s_or[t + o];
            __syncthreads();
        }
        if (t == 0) g_is64 = (s_or[0] == 0) ? 1 : 0;
    }
}

// ---------------- CSR build ----------------
__global__ void k_hist(const void* __restrict__ ei, int E) {
    int e = blockIdx.x * blockDim.x + threadIdx.x;
    int is64 = g_is64;
    if (e < E) atomicAdd(&g_deg[edge_at(ei, is64, (size_t)E + e)], 1);
}
__global__ void k_scan1() {
    __shared__ int s[256];
    int b = blockIdx.x, t = threadIdx.x;
    s[t] = g_deg[b * 256 + t];
    __syncthreads();
    for (int o = 128; o > 0; o >>= 1) {
        if (t < o) s[t] += s[t + o];
        __syncthreads();
    }
    if (t == 0) g_bsum[b] = s[0];
}
__global__ void k_scan2() {
    __shared__ int s[128];
    int t = threadIdx.x;
    int v = g_bsum[t];
    s[t] = v;
    __syncthreads();
    for (int off = 1; off < 128; off <<= 1) {
        int x = (t >= off) ? s[t - off] : 0;
        __syncthreads();
        s[t] += x;
        __syncthreads();
    }
    g_bsum[t] = s[t] - v;
    if (t == 127) g_rowptr[NN] = s[127];
}
__global__ void k_scan3() {
    __shared__ int s[256];
    int b = blockIdx.x, t = threadIdx.x;
    int i = b * 256 + t;
    int v = g_deg[i];
    s[t] = v;
    __syncthreads();
    for (int off = 1; off < 256; off <<= 1) {
        int x = (t >= off) ? s[t - off] : 0;
        __syncthreads();
        s[t] += x;
        __syncthreads();
    }
    int excl = s[t] - v + g_bsum[b];
    g_rowptr[i] = excl;
    g_cursor[i] = excl;
}
__global__ void k_scatter(const void* __restrict__ ei, int E) {
    int e = blockIdx.x * blockDim.x + threadIdx.x;
    int is64 = g_is64;
    if (e < E) {
        int s = edge_at(ei, is64, e);
        int d = edge_at(ei, is64, (size_t)E + e);
        g_csr[atomicAdd(&g_cursor[d], 1)] = s;
    } else if (e < E + NN) {
        int n = e - E;
        g_csr[atomicAdd(&g_cursor[n], 1)] = n;
    }
}

// ---------------- weight pretranspose + split ----------------
__global__ void k_prep(const float* __restrict__ W, int K, int Nn) {
    __shared__ float tile[32][33];
    int nb = blockIdx.x * 32, kb = blockIdx.y * 32;
    for (int j = threadIdx.y; j < 32; j += 8)
        tile[j][threadIdx.x] = W[(size_t)(kb + j) * Nn + nb + threadIdx.x];
    __syncthreads();
    for (int j = threadIdx.y; j < 32; j += 8) {
        float v = tile[threadIdx.x][j];
        __nv_bfloat16 hi = __float2bfloat16_rn(v);
        __nv_bfloat16 lo = __float2bfloat16_rn(v - __bfloat162float(hi));
        size_t o = (size_t)(nb + j) * K + kb + threadIdx.x;
        g_Bhi[o] = hi;
        g_Blo[o] = lo;
    }
}

// ---------------- activation conversion (BN+ReLU fused) -> bf16 hi/lo --------
// also zeroes g_asrc/g_adst (folded former k_zattn)
template <bool FUSE>
__global__ void k_conv(const float4* __restrict__ src, int kmask4) {
    int i = blockIdx.x * blockDim.x + threadIdx.x;
    if (i < NN * HH) { g_asrc[i] = 0.f; g_adst[i] = 0.f; }
    float4 v = src[i];
    if (FUSE) {
        int ch = (i & kmask4) * 4;
        v.x = fmaxf(fmaf(v.x, g_scale[ch + 0], g_shift[ch + 0]), 0.f);
        v.y = fmaxf(fmaf(v.y, g_scale[ch + 1], g_shift[ch + 1]), 0.f);
        v.z = fmaxf(fmaf(v.z, g_scale[ch + 2], g_shift[ch + 2]), 0.f);
        v.w = fmaxf(fmaf(v.w, g_scale[ch + 3], g_shift[ch + 3]), 0.f);
    }
    __nv_bfloat162 h0 = __floats2bfloat162_rn(v.x, v.y);
    __nv_bfloat162 h1 = __floats2bfloat162_rn(v.z, v.w);
    __nv_bfloat162 l0 = __floats2bfloat162_rn(v.x - __bfloat162float(h0.x),
                                              v.y - __bfloat162float(h0.y));
    __nv_bfloat162 l1 = __floats2bfloat162_rn(v.z - __bfloat162float(h1.x),
                                              v.w - __bfloat162float(h1.y));
    *(uint2*)&g_Ahi[(size_t)i * 4] = make_uint2(*(uint32_t*)&h0, *(uint32_t*)&h1);
    *(uint2*)&g_Alo[(size_t)i * 4] = make_uint2(*(uint32_t*)&l0, *(uint32_t*)&l1);
}

// ---------------- cp.async double-buffered bf16 mma GEMM ----------------
template <int K, bool ATTN, bool BIAS>
__global__ void __launch_bounds__(256) k_gemm_m(
    float* __restrict__ C, int Nn,
    const float* __restrict__ attS, const float* __restrict__ attD,
    const float* __restrict__ bias)
{
    constexpr int NC = K / 32;
    constexpr uint32_t STG = 40960;
    constexpr uint32_t OFF_AL = 10240, OFF_BH = 20480, OFF_BL = 30720;
    extern __shared__ __align__(16) char smraw[];
    const uint32_t sb = smem_u32(smraw);

    const int tid = threadIdx.x;
    const int lane = tid & 31;
    const int wid = tid >> 5;
    const int wm = wid & 3, wn = wid >> 2;
    const int row0 = blockIdx.y * 128, col0 = blockIdx.x * 128;

    float d[2][8][4];
#pragma unroll
    for (int i = 0; i < 2; i++)
#pragma unroll
        for (int j = 0; j < 8; j++)
#pragma unroll
            for (int q = 0; q < 4; q++) d[i][j][q] = 0.f;

    const int c0 = tid, c1 = tid + 256;
    const int r0s = c0 >> 2, kb0 = c0 & 3;
    const int r1s = c1 >> 2, kb1 = c1 & 3;

#define STAGE(kc, s) do { \
    uint32_t b = sb + (s) * STG; \
    cp16(b + r0s * 80 + kb0 * 16, &g_Ahi[(size_t)(row0 + r0s) * K + (kc) * 32 + kb0 * 8]); \
    cp16(b + r1s * 80 + kb1 * 16, &g_Ahi[(size_t)(row0 + r1s) * K + (kc) * 32 + kb1 * 8]); \
    cp16(b + OFF_AL + r0s * 80 + kb0 * 16, &g_Alo[(size_t)(row0 + r0s) * K + (kc) * 32 + kb0 * 8]); \
    cp16(b + OFF_AL + r1s * 80 + kb1 * 16, &g_Alo[(size_t)(row0 + r1s) * K + (kc) * 32 + kb1 * 8]); \
    cp16(b + OFF_BH + r0s * 80 + kb0 * 16, &g_Bhi[(size_t)(col0 + r0s) * K + (kc) * 32 + kb0 * 8]); \
    cp16(b + OFF_BH + r1s * 80 + kb1 * 16, &g_Bhi[(size_t)(col0 + r1s) * K + (kc) * 32 + kb1 * 8]); \
    cp16(b + OFF_BL + r0s * 80 + kb0 * 16, &g_Blo[(size_t)(col0 + r0s) * K + (kc) * 32 + kb0 * 8]); \
    cp16(b + OFF_BL + r1s * 80 + kb1 * 16, &g_Blo[(size_t)(col0 + r1s) * K + (kc) * 32 + kb1 * 8]); \
} while (0)

    STAGE(0, 0);
    CP_COMMIT();

    const int a_row = lane & 15, a_col8 = (lane >> 4) * 8;
    const int b_row = ((lane >> 4) << 3) + (lane & 7), b_col8 = ((lane >> 3) & 1) * 8;

    for (int kc = 0; kc < NC; ++kc) {
        if (kc + 1 < NC) {
            STAGE(kc + 1, (kc + 1) & 1);
            CP_COMMIT();
            asm volatile("cp.async.wait_group 1;" ::: "memory");
        } else {
            asm volatile("cp.async.wait_group 0;" ::: "memory");
        }
        __syncthreads();

        const uint32_t bs = sb + (kc & 1) * STG;
#pragma unroll
        for (int kk = 0; kk < 32; kk += 16) {
            uint32_t ah[2][4], al[2][4], bh[8][2], bl[8][2];
#pragma unroll
            for (int mi = 0; mi < 2; mi++) {
                uint32_t off = (uint32_t)((wm * 32 + mi * 16 + a_row) * 40 + kk + a_col8) * 2;
                LDSM_X4(ah[mi][0], ah[mi][1], ah[mi][2], ah[mi][3], bs + off);
                LDSM_X4(al[mi][0], al[mi][1], al[mi][2], al[mi][3], bs + OFF_AL + off);
            }
#pragma unroll
            for (int np = 0; np < 4; np++) {
                uint32_t off = (uint32_t)((wn * 64 + np * 16 + b_row) * 40 + kk + b_col8) * 2;
                uint32_t r0, r1, r2, r3;
                LDSM_X4(r0, r1, r2, r3, bs + OFF_BH + off);
                bh[np * 2][0] = r0; bh[np * 2][1] = r1;
                bh[np * 2 + 1][0] = r2; bh[np * 2 + 1][1] = r3;
                LDSM_X4(r0, r1, r2, r3, bs + OFF_BL + off);
                bl[np * 2][0] = r0; bl[np * 2][1] = r1;
                bl[np * 2 + 1][0] = r2; bl[np * 2 + 1][1] = r3;
            }
#pragma unroll
            for (int mi = 0; mi < 2; mi++)
#pragma unroll
                for (int ni = 0; ni < 8; ni++) {
                    MMA16816(d[mi][ni], ah[mi][0], ah[mi][1], ah[mi][2], ah[mi][3],
                             bh[ni][0], bh[ni][1]);
                    MMA16816(d[mi][ni], ah[mi][0], ah[mi][1], ah[mi][2], ah[mi][3],
                             bl[ni][0], bl[ni][1]);
                    MMA16816(d[mi][ni], al[mi][0], al[mi][1], al[mi][2], al[mi][3],
                             bh[ni][0], bh[ni][1]);
                }
        }
        __syncthreads();
    }
#undef STAGE

    const int er = lane >> 2, ec = (lane & 3) * 2;
#pragma unroll
    for (int mi = 0; mi < 2; mi++) {
        float s0 = 0.f, s1 = 0.f, t0 = 0.f, t1 = 0.f;
#pragma unroll
        for (int ni = 0; ni < 8; ni++) {
            int r = row0 + wm * 32 + mi * 16 + er;
            int c = col0 + wn * 64 + ni * 8 + ec;
            float2 v0 = make_float2(d[mi][ni][0], d[mi][ni][1]);
            float2 v1 = make_float2(d[mi][ni][2], d[mi][ni][3]);
            if (BIAS) {
                float b0 = __ldg(&bias[c]), b1 = __ldg(&bias[c + 1]);
                v0.x += b0; v0.y += b1; v1.x += b0; v1.y += b1;
            }
            if (ATTN) {
                int cc = wn * 64 + ni * 8 + ec;
                int head = blockIdx.x;
                float a0 = __ldg(&attS[head * CC + cc]);
                float a1 = __ldg(&attS[head * CC + cc + 1]);
                float e0 = __ldg(&attD[head * CC + cc]);
                float e1 = __ldg(&attD[head * CC + cc + 1]);
                s0 = fmaf(v0.x, a0, fmaf(v0.y, a1, s0));
                s1 = fmaf(v1.x, a0, fmaf(v1.y, a1, s1));
                t0 = fmaf(v0.x, e0, fmaf(v0.y, e1, t0));
                t1 = fmaf(v1.x, e0, fmaf(v1.y, e1, t1));
            }
            *(float2*)&C[(size_t)r * Nn + c] = v0;
            *(float2*)&C[(size_t)(r + 8) * Nn + c] = v1;
        }
        if (ATTN) {
            s0 += __shfl_xor_sync(0xffffffffu, s0, 1);
            s0 += __shfl_xor_sync(0xffffffffu, s0, 2);
            s1 += __shfl_xor_sync(0xffffffffu, s1, 1);
            s1 += __shfl_xor_sync(0xffffffffu, s1, 2);
            t0 += __shfl_xor_sync(0xffffffffu, t0, 1);
            t0 += __shfl_xor_sync(0xffffffffu, t0, 2);
            t1 += __shfl_xor_sync(0xffffffffu, t1, 1);
            t1 += __shfl_xor_sync(0xffffffffu, t1, 2);
            if ((lane & 3) == 0) {
                int head = blockIdx.x;
                int r = row0 + wm * 32 + mi * 16 + er;
                atomicAdd(&g_asrc[r * 4 + head], s0);
                atomicAdd(&g_adst[r * 4 + head], t0);
                atomicAdd(&g_asrc[(r + 8) * 4 + head], s1);
                atomicAdd(&g_adst[(r + 8) * 4 + head], t1);
            }
        }
    }
}

__device__ __forceinline__ float lrelu(float v) { return v > 0.f ? v : NEG * v; }

// ---------------- segment softmax + aggregation: SINGLE PASS ----------------
// warp per dst node (proven best shape). Softmax shift-invariance: accumulate
// num = sum(exp(e)*h) and den = sum(exp(e)) in one sweep — no max pass, no
// denom pass. Logits bounded (|e| <~ 15) so exp(e) is fp32-safe.
__global__ void __launch_bounds__(256) k_aggr(const float* __restrict__ h,
                                              const float* __restrict__ bias)
{
    __shared__ float s_sum[CC], s_sq[CC];
    int tid = threadIdx.x;
    if (tid < CC) { s_sum[tid] = 0.f; s_sq[tid] = 0.f; }
    __syncthreads();

    int lane = tid & 31;
    int n = blockIdx.x * 8 + (tid >> 5);
    int start = g_rowptr[n], end = g_rowptr[n + 1];
    float4 ad = *(const float4*)&g_adst[n * 4];

    const float4* hp = (const float4*)h;
    float4 a0 = make_float4(0.f, 0.f, 0.f, 0.f), a1 = a0, a2 = a0, a3 = a0;
    float d0 = 0.f, d1 = 0.f, d2 = 0.f, d3 = 0.f;
    for (int i = start; i < end; ++i) {
        int s = g_csr[i];
        float4 as = *(const float4*)&g_asrc[s * 4];
        float w0 = __expf(lrelu(as.x + ad.x));
        float w1 = __expf(lrelu(as.y + ad.y));
        float w2 = __expf(lrelu(as.z + ad.z));
        float w3 = __expf(lrelu(as.w + ad.w));
        d0 += w0; d1 += w1; d2 += w2; d3 += w3;
        size_t base = (size_t)s * 128;
        float4 v;
        v = hp[base + lane];
        a0.x = fmaf(v.x, w0, a0.x); a0.y = fmaf(v.y, w0, a0.y);
        a0.z = fmaf(v.z, w0, a0.z); a0.w = fmaf(v.w, w0, a0.w);
        v = hp[base + 32 + lane];
        a1.x = fmaf(v.x, w1, a1.x); a1.y = fmaf(v.y, w1, a1.y);
        a1.z = fmaf(v.z, w1, a1.z); a1.w = fmaf(v.w, w1, a1.w);
        v = hp[base + 64 + lane];
        a2.x = fmaf(v.x, w2, a2.x); a2.y = fmaf(v.y, w2, a2.y);
        a2.z = fmaf(v.z, w2, a2.z); a2.w = fmaf(v.w, w2, a2.w);
        v = hp[base + 96 + lane];
        a3.x = fmaf(v.x, w3, a3.x); a3.y = fmaf(v.y, w3, a3.y);
        a3.z = fmaf(v.z, w3, a3.z); a3.w = fmaf(v.w, w3, a3.w);
    }
    float i0 = 1.f / (d0 + 1e-16f), i1 = 1.f / (d1 + 1e-16f);
    float i2 = 1.f / (d2 + 1e-16f), i3 = 1.f / (d3 + 1e-16f);

    float4 bb = ((const float4*)bias)[lane];
    float4 o;
    o.x = 0.25f * (a0.x * i0 + a1.x * i1 + a2.x * i2 + a3.x * i3) + bb.x;
    o.y = 0.25f * (a0.y * i0 + a1.y * i1 + a2.y * i2 + a3.y * i3) + bb.y;
    o.z = 0.25f * (a0.z * i0 + a1.z * i1 + a2.z * i2 + a3.z * i3) + bb.z;
    o.w = 0.25f * (a0.w * i0 + a1.w * i1 + a2.w * i2 + a3.w * i3) + bb.w;
    ((float4*)g_t)[(size_t)n * 32 + lane] = o;

    int c = lane * 4;
    atomicAdd(&s_sum[c + 0], o.x); atomicAdd(&s_sq[c + 0], o.x * o.x);
    atomicAdd(&s_sum[c + 1], o.y); atomicAdd(&s_sq[c + 1], o.y * o.y);
    atomicAdd(&s_sum[c + 2], o.z); atomicAdd(&s_sq[c + 2], o.z * o.z);
    atomicAdd(&s_sum[c + 3], o.w); atomicAdd(&s_sq[c + 3], o.w * o.w);
    __syncthreads();
    if (tid < CC) {
        atomicAdd(&g_bnsum[tid], s_sum[tid]);
        atomicAdd(&g_bnsq[tid], s_sq[tid]);
    }
}

__global__ void k_bnfin(const float* __restrict__ g, const float* __restrict__ be) {
    int c = threadIdx.x;
    float mu = g_bnsum[c] * (1.f / NN);
    float var = g_bnsq[c] * (1.f / NN) - mu * mu;
    float sc = g[c] * rsqrtf(var + 1e-5f);
    g_scale[c] = sc;
    g_shift[c] = be[c] - mu * sc;
    g_bnsum[c] = 0.f;
    g_bnsq[c] = 0.f;
}

// ---------------- launch ----------------
extern "C" void kernel_launch(void* const* d_in, const int* in_sizes, int n_in,
                              void* d_out, int out_size)
{
    const float* x   = (const float*)d_in[0];
    const void*  ei  = d_in[1];
    const float* W1  = (const float*)d_in[2];
    const float* as1 = (const float*)d_in[3];
    const float* ad1 = (const float*)d_in[4];
    const float* b1  = (const float*)d_in[5];
    const float* g1  = (const float*)d_in[6];
    const float* be1 = (const float*)d_in[7];
    const float* W2  = (const float*)d_in[8];
    const float* as2 = (const float*)d_in[9];
    const float* ad2 = (const float*)d_in[10];
    const float* b2  = (const float*)d_in[11];
    const float* g2  = (const float*)d_in[12];
    const float* be2 = (const float*)d_in[13];
    const float* Wf  = (const float*)d_in[14];
    const float* bf  = (const float*)d_in[15];
    int E = in_sizes[1] / 2;

    float *ph = nullptr, *pt = nullptr;
    cudaGetSymbolAddress((void**)&ph, g_h);
    cudaGetSymbolAddress((void**)&pt, g_t);
    float* out = (float*)d_out;

    constexpr int SMEM = 81920;
    cudaFuncSetAttribute(k_gemm_m<256, true, false>,
                         cudaFuncAttributeMaxDynamicSharedMemorySize, SMEM);
    cudaFuncSetAttribute(k_gemm_m<128, true, false>,
                         cudaFuncAttributeMaxDynamicSharedMemorySize, SMEM);
    cudaFuncSetAttribute(k_gemm_m<128, false, true>,
                         cudaFuncAttributeMaxDynamicSharedMemorySize, SMEM);

    // layer-1 GEMM chain
    k_prep<<<dim3(HC / 32, FIN / 32), dim3(32, 8)>>>(W1, FIN, HC);
    k_conv<false><<<NN * FIN / 1024, 256>>>((const float4*)x, FIN / 4 - 1);
    k_gemm_m<256, true, false><<<dim3(4, 256), 256, SMEM>>>(ph, HC, as1, ad1, nullptr);

    // CSR build
    k_initdet<<<NN / 256, 256>>>((const unsigned int*)ei);
    k_hist<<<(E + 255) / 256, 256>>>(ei, E);
    k_scan1<<<128, 256>>>();
    k_scan2<<<1, 128>>>();
    k_scan3<<<128, 256>>>();
    k_scatter<<<(E + NN + 255) / 256, 256>>>(ei, E);

    k_aggr<<<4096, 256>>>(ph, b1);
    k_bnfin<<<1, 128>>>(g1, be1);

    // layer 2
    k_prep<<<dim3(HC / 32, CC / 32), dim3(32, 8)>>>(W2, CC, HC);
    k_conv<true><<<NN * CC / 1024, 256>>>((const float4*)pt, CC / 4 - 1);
    k_gemm_m<128, true, false><<<dim3(4, 256), 256, SMEM>>>(ph, HC, as2, ad2, nullptr);
    k_aggr<<<4096, 256>>>(ph, b2);
    k_bnfin<<<1, 128>>>(g2, be2);

    // final linear (fp32 out)
    k_prep<<<dim3(CC / 32, CC / 32), dim3(32, 8)>>>(Wf, CC, CC);
    k_conv<true><<<NN * CC / 1024, 256>>>((const float4*)pt, CC / 4 - 1);
    k_gemm_m<128, false, true><<<dim3(1, 256), 256, SMEM>>>(out, CC, nullptr, nullptr, bf);
}